// round 9
// baseline (speedup 1.0000x reference)
#include <cuda_runtime.h>
#include <cstdint>
#include <math.h>

// B fragments, sparsity-compacted, mma-fragment order: [tap 125][frag 40][64 floats]
// frag schedule per slice: ks0,ks1 -> nt 0..7 (frags 0..15);
// ks>=2 -> frags 16+(ks-2)*4+{0..3} = nt {0,1, 2+2j, 3+2j}, j=(ks-2)>>1.
__device__ float BF[125 * 2560];
// x tf32-rounded + channel-permuted into groups [S, V0, V1, V2]
__device__ float XT[64 * 175616];

#define OS3 140608   // 52^3
#define OS2 2704     // 52^2

// ---------------------------------------------------------------------------
// Builder (original (ic,oc) logic, skip folded into center tap; destination
// indices permuted: c' = c<16 ? c : 16 + i3*16 + u  where c = 16+3u+i3)
// ---------------------------------------------------------------------------
__global__ void build_kernel(const float* __restrict__ weight,
                             const float* __restrict__ w_sc0,
                             const float* __restrict__ w_sc1) {
    int tap = blockIdx.x;
    int kd = tap / 25, kh = (tap / 5) % 5, kw = tap % 5;

    float rx = -1.f + 0.5f * kd, ry = -1.f + 0.5f * kh, rz = -1.f + 0.5f * kw;
    float d = sqrtf(rx * rx + ry * ry + rz * rz);
    const float C = 1.14136f * 7.38905609893065f;   // 1.14136 * e^2
    float emb[5];
#pragma unroll
    for (int m = 0; m < 5; m++) {
        float diff = 4.f * d - (float)m;
        float t1 = diff + 1.f, t2 = 1.f - diff;
        float s1 = (t1 > 0.f) ? expf(-1.f / t1) : 0.f;
        float s2 = (t2 > 0.f) ? expf(-1.f / t2) : 0.f;
        emb[m] = C * s1 * s2;
    }
    float dinv = 1.f / fmaxf(d, 1e-12f);
    const float SQ3 = 1.7320508075688772f;
    float sh1[3] = { SQ3 * rx * dinv, SQ3 * ry * dinv, SQ3 * rz * dinv };
    const float PW0 = 0.1767766952966369f, INV_SQRT3 = 0.5773502691896258f;
    bool center = (kd == 2 && kh == 2 && kw == 2);

    for (int e = threadIdx.x; e < 4096; e += blockDim.x) {
        int ic = e >> 6, oc = e & 63;
        float val = 0.f;
        bool dead = false;
        if (ic < 16 && oc < 16) {
            int c = ic * 16 + oc; float wv = 0.f;
#pragma unroll
            for (int m = 0; m < 5; m++) wv += emb[m] * weight[m * 1024 + c];
            val = PW0 * wv;
            if (center) val += 0.25f * w_sc0[ic * 16 + oc];
        } else if (ic < 16) {
            int o = oc - 16, w2 = o / 3, k3 = o - 3 * w2;
            int c = 256 + ic * 16 + w2; float wv = 0.f;
#pragma unroll
            for (int m = 0; m < 5; m++) wv += emb[m] * weight[m * 1024 + c];
            val = PW0 * wv * sh1[k3];
        } else if (oc < 16) {
            int iv = ic - 16, u = iv / 3, i3 = iv - 3 * u;
            int c = 768 + u * 16 + oc; float wv = 0.f;
#pragma unroll
            for (int m = 0; m < 5; m++) wv += emb[m] * weight[m * 1024 + c];
            val = PW0 * INV_SQRT3 * wv * sh1[i3];
        } else {
            int iv = ic - 16, ov = oc - 16;
            int u = iv / 3, i3 = iv - 3 * u, w2 = ov / 3, j3 = ov - 3 * w2;
            if (i3 == j3) {
                int c = 512 + u * 16 + w2; float wv = 0.f;
#pragma unroll
                for (int m = 0; m < 5; m++) wv += emb[m] * weight[m * 1024 + c];
                val = PW0 * wv;
                if (center) val += 0.25f * w_sc1[u * 16 + w2];
            } else dead = true;
        }
        if (dead) continue;

        int icp = ic < 16 ? ic : 16 + ((ic - 16) % 3) * 16 + (ic - 16) / 3;
        int ocp = oc < 16 ? oc : 16 + ((oc - 16) % 3) * 16 + (oc - 16) / 3;
        int ks = icp >> 3, k7 = icp & 7;
        int rr = k7 >> 2, lanei = (ocp & 7) * 4 + (k7 & 3), nt = ocp >> 3;
        int f;
        if (ks < 2) f = ks * 8 + nt;
        else if (nt < 2) f = 16 + (ks - 2) * 4 + nt;
        else f = 16 + (ks - 2) * 4 + 2 + (nt & 1);   // nt = {2+2j, 3+2j}
        uint32_t v;
        asm("cvt.rna.tf32.f32 %0, %1;" : "=r"(v) : "f"(val));
        ((uint32_t*)BF)[tap * 2560 + f * 64 + lanei * 2 + rr] = v;
    }
}

// Pre-convert x to tf32 (rna) + channel permutation. 2744*1024 float4s.
__global__ void cvt_x_kernel(const float* __restrict__ x) {
    int i = blockIdx.x * 1024 + threadIdx.x;
    int c = i / 43904, rem = i - c * 43904;       // 43904 float4 per channel
    float4 v = ((const float4*)x)[i];
    uint4 o;
    asm("cvt.rna.tf32.f32 %0, %1;" : "=r"(o.x) : "f"(v.x));
    asm("cvt.rna.tf32.f32 %0, %1;" : "=r"(o.y) : "f"(v.y));
    asm("cvt.rna.tf32.f32 %0, %1;" : "=r"(o.z) : "f"(v.z));
    asm("cvt.rna.tf32.f32 %0, %1;" : "=r"(o.w) : "f"(v.w));
    int cp = c < 16 ? c : 16 + ((c - 16) % 3) * 16 + (c - 16) / 3;
    ((uint4*)XT)[cp * 43904 + rem] = o;
}

// ---------------------------------------------------------------------------
static __device__ __forceinline__ void cp16(uint32_t saddr, const float* g) {
    asm volatile("cp.async.cg.shared.global [%0], [%1], 16;"
                 :: "r"(saddr), "l"(g) : "memory");
}
static __device__ __forceinline__ void mma_tf32(float c[4], const uint32_t a[4],
                                                uint32_t b0, uint32_t b1) {
    asm volatile("mma.sync.aligned.m16n8k8.row.col.f32.tf32.tf32.f32 "
                 "{%0,%1,%2,%3}, {%4,%5,%6,%7}, {%8,%9}, {%0,%1,%2,%3};"
                 : "+f"(c[0]), "+f"(c[1]), "+f"(c[2]), "+f"(c[3])
                 : "r"(a[0]), "r"(a[1]), "r"(a[2]), "r"(a[3]), "r"(b0), "r"(b1));
}

// ---------------------------------------------------------------------------
// Conv: CTA = 4 output rows, 256 threads / 8 warps.
// warp = mh*4 + r: row r, M-half mh (ow 0..31 / 32..63). N=64 oc', K=64 ic'.
// smem: xs[4][64][72] (73728 B) + B ring 4 x 10240 B = 114688 B.
// One __syncthreads per slice; 4-slot cp.async ring, prefetch distance 3.
// ---------------------------------------------------------------------------
__global__ void __launch_bounds__(256, 1) conv_kernel(float* __restrict__ out) {
    extern __shared__ float sm[];
    float* xs = sm;                 // 18432 floats
    float* Bs = sm + 18432;         // 4 * 2560 floats

    int tid = threadIdx.x, warp = tid >> 5, lane = tid & 31;
    int r = warp & 3, mh = warp >> 2;
    int row0 = blockIdx.x * 4;

    uint32_t bs_u = (uint32_t)__cvta_generic_to_shared(Bs);

    // zero the w-pad region [56..72)
    for (int i = tid; i < 4096; i += 256) {
        int r2 = i >> 10, rem = i & 1023, ic = rem >> 4;
        xs[(r2 * 64 + ic) * 72 + 56 + (rem & 15)] = 0.f;
    }

    // prefetch slices 0..2
    const float* bf = BF;
#pragma unroll 1
    for (int sl = 0; sl < 3; sl++) {
        for (int i = tid; i < 640; i += 256)
            cp16(bs_u + (uint32_t)(sl * 10240 + i * 16), bf + sl * 2560 + i * 4);
        asm volatile("cp.async.commit_group;" ::: "memory");
    }

    float acc[2][8][4];
#pragma unroll
    for (int mtl = 0; mtl < 2; mtl++)
#pragma unroll
        for (int nt = 0; nt < 8; nt++)
#pragma unroll
            for (int q = 0; q < 4; q++) acc[mtl][nt][q] = 0.f;

    for (int g = 0; g < 25; g++) {
        int gd = g / 5, gh = g - gd * 5;
#pragma unroll 1
        for (int kw = 0; kw < 5; kw++) {
            int s = g * 5 + kw;
            asm volatile("cp.async.wait_group 2;" ::: "memory");
            __syncthreads();           // slice s visible; all warps done with s-1

            if (kw == 0) {             // reload xs for this (gd, gh)
                for (int i = tid; i < 3584; i += 256) {
                    int r2 = i / 896, rem = i - r2 * 896;
                    int ic = rem / 14, wv = rem - ic * 14;
                    int rowx = row0 + r2, odx = rowx / 52, ohx = rowx - odx * 52;
                    float4 v = *(const float4*)&XT[ic * 175616 + (odx + gd) * 3136 +
                                                   (ohx + gh) * 56 + wv * 4];
                    *(float4*)&xs[(r2 * 64 + ic) * 72 + wv * 4] = v;
                }
                __syncthreads();
            }

            // prefetch slice s+3 into slot (s+3)&3 (held slice s-1: retired above)
            if (s + 3 < 125) {
                const float* src = bf + (s + 3) * 2560;
                uint32_t dst = bs_u + (uint32_t)(((s + 3) & 3) * 10240);
                for (int i = tid; i < 640; i += 256)
                    cp16(dst + (uint32_t)(i * 16), src + i * 4);
            }
            asm volatile("cp.async.commit_group;" ::: "memory");

            const float* Bp = Bs + (s & 3) * 2560;
            const float* Ap = xs + r * 4608 + (lane & 3) * 72 + (lane >> 2) + kw + mh * 32;

#pragma unroll
            for (int ks = 0; ks < 8; ks++) {
                uint32_t a[2][4];
#pragma unroll
                for (int mtl = 0; mtl < 2; mtl++) {
                    const float* p = Ap + ks * 576 + mtl * 16;
                    a[mtl][0] = __float_as_uint(p[0]);
                    a[mtl][1] = __float_as_uint(p[8]);
                    a[mtl][2] = __float_as_uint(p[288]);
                    a[mtl][3] = __float_as_uint(p[296]);
                }
                if (ks < 2) {
#pragma unroll
                    for (int nt = 0; nt < 8; nt++) {
                        uint2 bb = *(const uint2*)&Bp[(ks * 8 + nt) * 64 + lane * 2];
                        mma_tf32(acc[0][nt], a[0], bb.x, bb.y);
                        mma_tf32(acc[1][nt], a[1], bb.x, bb.y);
                    }
                } else {
                    int j2 = ((ks - 2) >> 1) * 2;          // 0, 2, 4
                    int fb = 16 + (ks - 2) * 4;
#pragma unroll
                    for (int q = 0; q < 4; q++) {
                        int nt = (q < 2) ? q : (2 + j2 + (q - 2));
                        uint2 bb = *(const uint2*)&Bp[(fb + q) * 64 + lane * 2];
                        mma_tf32(acc[0][nt], a[0], bb.x, bb.y);
                        mma_tf32(acc[1][nt], a[1], bb.x, bb.y);
                    }
                }
            }
        }
    }

    // Epilogue: acc holds out[ow][oc'] for row (row0 + r), ow-half mh.
    int myrow = row0 + r, myod = myrow / 52, myoh = myrow - myod * 52;
    int base = myod * OS2 + myoh * 52;
#pragma unroll
    for (int mtl = 0; mtl < 2; mtl++) {
        int ow = mh * 32 + mtl * 16 + (lane >> 2);
#pragma unroll
        for (int nt = 0; nt < 8; nt++) {
            int ocp = nt * 8 + (lane & 3) * 2;
            int oc0 = ocp < 16 ? ocp : 16 + 3 * ((ocp - 16) & 15) + ((ocp - 16) >> 4);
            int op1 = ocp + 1;
            int oc1 = op1 < 16 ? op1 : 16 + 3 * ((op1 - 16) & 15) + ((op1 - 16) >> 4);
            if (ow < 52) {
                out[oc0 * OS3 + base + ow] = acc[mtl][nt][0];
                out[oc1 * OS3 + base + ow] = acc[mtl][nt][1];
            }
            if (ow + 8 < 52) {
                out[oc0 * OS3 + base + ow + 8] = acc[mtl][nt][2];
                out[oc1 * OS3 + base + ow + 8] = acc[mtl][nt][3];
            }
        }
    }
}

// ---------------------------------------------------------------------------
extern "C" void kernel_launch(void* const* d_in, const int* in_sizes, int n_in,
                              void* d_out, int out_size) {
    const float* x      = (const float*)d_in[0];   // (1, 64, 56, 56, 56)
    const float* weight = (const float*)d_in[1];   // (5, 1024)
    const float* w_sc0  = (const float*)d_in[2];   // (16, 16)
    const float* w_sc1  = (const float*)d_in[3];   // (16, 16)
    float* out = (float*)d_out;                    // (1, 64, 52, 52, 52)

    cudaFuncSetAttribute(conv_kernel, cudaFuncAttributeMaxDynamicSharedMemorySize, 114688);
    build_kernel<<<125, 256>>>(weight, w_sc0, w_sc1);
    cvt_x_kernel<<<2744, 1024>>>(x);
    conv_kernel<<<676, 256, 114688>>>(out);
}

// round 10
// speedup vs baseline: 1.7215x; 1.7215x over previous
#include <cuda_runtime.h>
#include <cstdint>
#include <math.h>

// B fragments, sparsity-compacted, mma-fragment order: [tap 125][frag 40][64 floats]
// frag schedule per slice: ks0,ks1 -> nt 0..7 (frags 0..15);
// ks>=2 -> frags 16+(ks-2)*4+{0..3} = nt {0,1, 2+2j, 3+2j}, j=(ks-2)>>1.
__device__ float BF[125 * 2560];
// x tf32-rounded + channel-permuted into groups [S, V0, V1, V2]
__device__ float XT[64 * 175616];

#define OS3 140608   // 52^3
#define OS2 2704     // 52^2

// ---------------------------------------------------------------------------
// Builder: channel matrix per tap (skip folded into center tap), permuted
// (c' = c<16 ? c : 16 + i3*16 + u for c = 16+3u+i3), packed into 40 fragments.
// ---------------------------------------------------------------------------
__global__ void build_kernel(const float* __restrict__ weight,
                             const float* __restrict__ w_sc0,
                             const float* __restrict__ w_sc1) {
    int tap = blockIdx.x;
    int kd = tap / 25, kh = (tap / 5) % 5, kw = tap % 5;

    float rx = -1.f + 0.5f * kd, ry = -1.f + 0.5f * kh, rz = -1.f + 0.5f * kw;
    float d = sqrtf(rx * rx + ry * ry + rz * rz);
    const float C = 1.14136f * 7.38905609893065f;   // 1.14136 * e^2
    float emb[5];
#pragma unroll
    for (int m = 0; m < 5; m++) {
        float diff = 4.f * d - (float)m;
        float t1 = diff + 1.f, t2 = 1.f - diff;
        float s1 = (t1 > 0.f) ? expf(-1.f / t1) : 0.f;
        float s2 = (t2 > 0.f) ? expf(-1.f / t2) : 0.f;
        emb[m] = C * s1 * s2;
    }
    float dinv = 1.f / fmaxf(d, 1e-12f);
    const float SQ3 = 1.7320508075688772f;
    float sh1[3] = { SQ3 * rx * dinv, SQ3 * ry * dinv, SQ3 * rz * dinv };
    const float PW0 = 0.1767766952966369f, INV_SQRT3 = 0.5773502691896258f;
    bool center = (kd == 2 && kh == 2 && kw == 2);

    for (int e = threadIdx.x; e < 4096; e += blockDim.x) {
        int ic = e >> 6, oc = e & 63;
        float val = 0.f;
        bool dead = false;
        if (ic < 16 && oc < 16) {
            int c = ic * 16 + oc; float wv = 0.f;
#pragma unroll
            for (int m = 0; m < 5; m++) wv += emb[m] * weight[m * 1024 + c];
            val = PW0 * wv;
            if (center) val += 0.25f * w_sc0[ic * 16 + oc];
        } else if (ic < 16) {
            int o = oc - 16, w2 = o / 3, k3 = o - 3 * w2;
            int c = 256 + ic * 16 + w2; float wv = 0.f;
#pragma unroll
            for (int m = 0; m < 5; m++) wv += emb[m] * weight[m * 1024 + c];
            val = PW0 * wv * sh1[k3];
        } else if (oc < 16) {
            int iv = ic - 16, u = iv / 3, i3 = iv - 3 * u;
            int c = 768 + u * 16 + oc; float wv = 0.f;
#pragma unroll
            for (int m = 0; m < 5; m++) wv += emb[m] * weight[m * 1024 + c];
            val = PW0 * INV_SQRT3 * wv * sh1[i3];
        } else {
            int iv = ic - 16, ov = oc - 16;
            int u = iv / 3, i3 = iv - 3 * u, w2 = ov / 3, j3 = ov - 3 * w2;
            if (i3 == j3) {
                int c = 512 + u * 16 + w2; float wv = 0.f;
#pragma unroll
                for (int m = 0; m < 5; m++) wv += emb[m] * weight[m * 1024 + c];
                val = PW0 * wv;
                if (center) val += 0.25f * w_sc1[u * 16 + w2];
            } else dead = true;
        }
        if (dead) continue;

        int icp = ic < 16 ? ic : 16 + ((ic - 16) % 3) * 16 + (ic - 16) / 3;
        int ocp = oc < 16 ? oc : 16 + ((oc - 16) % 3) * 16 + (oc - 16) / 3;
        int ks = icp >> 3, k7 = icp & 7;
        int rr = k7 >> 2, lanei = (ocp & 7) * 4 + (k7 & 3), nt = ocp >> 3;
        int f;
        if (ks < 2) f = ks * 8 + nt;
        else if (nt < 2) f = 16 + (ks - 2) * 4 + nt;
        else f = 16 + (ks - 2) * 4 + 2 + (nt & 1);   // nt = {2+2j, 3+2j}
        uint32_t v;
        asm("cvt.rna.tf32.f32 %0, %1;" : "=r"(v) : "f"(val));
        ((uint32_t*)BF)[tap * 2560 + f * 64 + lanei * 2 + rr] = v;
    }
}

// Pre-convert x to tf32 (rna) + channel permutation. 2744*1024 float4s.
__global__ void cvt_x_kernel(const float* __restrict__ x) {
    int i = blockIdx.x * 1024 + threadIdx.x;
    int c = i / 43904, rem = i - c * 43904;       // 43904 float4 per channel
    float4 v = ((const float4*)x)[i];
    uint4 o;
    asm("cvt.rna.tf32.f32 %0, %1;" : "=r"(o.x) : "f"(v.x));
    asm("cvt.rna.tf32.f32 %0, %1;" : "=r"(o.y) : "f"(v.y));
    asm("cvt.rna.tf32.f32 %0, %1;" : "=r"(o.z) : "f"(v.z));
    asm("cvt.rna.tf32.f32 %0, %1;" : "=r"(o.w) : "f"(v.w));
    int cp = c < 16 ? c : 16 + ((c - 16) % 3) * 16 + (c - 16) / 3;
    ((uint4*)XT)[cp * 43904 + rem] = o;
}

// ---------------------------------------------------------------------------
static __device__ __forceinline__ void cp16(uint32_t saddr, const float* g) {
    asm volatile("cp.async.cg.shared.global [%0], [%1], 16;"
                 :: "r"(saddr), "l"(g) : "memory");
}
static __device__ __forceinline__ void mma_tf32(float c[4], const uint32_t a[4],
                                                uint32_t b0, uint32_t b1) {
    asm volatile("mma.sync.aligned.m16n8k8.row.col.f32.tf32.tf32.f32 "
                 "{%0,%1,%2,%3}, {%4,%5,%6,%7}, {%8,%9}, {%0,%1,%2,%3};"
                 : "+f"(c[0]), "+f"(c[1]), "+f"(c[2]), "+f"(c[3])
                 : "r"(a[0]), "r"(a[1]), "r"(a[2]), "r"(a[3]), "r"(b0), "r"(b1));
}

// ---------------------------------------------------------------------------
// Conv: CTA = 4 output rows (row = od*52+oh). 128 threads; warp w owns row w:
// M=64 (ow 0..63, valid <52), N=64 oc', 128 accum regs/lane.
// R8 flow exactly; only the B schedule is sparsity-compacted (40 frags/slice).
// smem: xs[4][ic 64][w 72] (73728 B) + B ring 2 x 10240 B = 94208 B.
// ---------------------------------------------------------------------------
__global__ void __launch_bounds__(128, 1) conv_kernel(float* __restrict__ out) {
    extern __shared__ float sm[];
    float* xs = sm;                 // 18432 floats
    float* Bs = sm + 18432;         // 2 * 2560 floats

    int tid = threadIdx.x, warp = tid >> 5, lane = tid & 31;
    int row0 = blockIdx.x * 4;
    int myrow = row0 + warp, myod = myrow / 52, myoh = myrow - myod * 52;

    uint32_t bs_u = (uint32_t)__cvta_generic_to_shared(Bs);

    // zero the w-pad region [56..72) once
    for (int i = tid; i < 4096; i += 128) {
        int r2 = i >> 10, rem = i & 1023, ic = rem >> 4, w = 56 + (rem & 15);
        xs[(r2 * 64 + ic) * 72 + w] = 0.f;
    }

    // prefetch B slices 0 and 1
    const float* bf = BF;
#pragma unroll 1
    for (int sl = 0; sl < 2; sl++) {
        for (int i = tid; i < 640; i += 128)
            cp16(bs_u + (uint32_t)(sl * 10240 + i * 16), bf + sl * 2560 + i * 4);
        asm volatile("cp.async.commit_group;" ::: "memory");
    }

    float acc[4][8][4];
#pragma unroll
    for (int mt = 0; mt < 4; mt++)
#pragma unroll
        for (int nt = 0; nt < 8; nt++)
#pragma unroll
            for (int q = 0; q < 4; q++) acc[mt][nt][q] = 0.f;

    for (int g = 0; g < 25; g++) {
        int gd = g / 5, gh = g - gd * 5;
        __syncthreads();   // all warps done with previous xs
        for (int i = tid; i < 3584; i += 128) {
            int r2 = i / 896, rem = i - r2 * 896;
            int ic = rem / 14, wv = rem - ic * 14;
            int rowx = row0 + r2, odx = rowx / 52, ohx = rowx - odx * 52;
            float4 v = *(const float4*)&XT[ic * 175616 + (odx + gd) * 3136 +
                                           (ohx + gh) * 56 + wv * 4];
            *(float4*)&xs[(r2 * 64 + ic) * 72 + wv * 4] = v;
        }
        __syncthreads();

        for (int kw = 0; kw < 5; kw++) {
            int s = g * 5 + kw;
            asm volatile("cp.async.wait_group 1;" ::: "memory");
            __syncthreads();            // slice s visible to all warps

            const float* Bp = Bs + (s & 1) * 2560;
            const float* Ap = xs + warp * 4608 + (lane & 3) * 72 + (lane >> 2) + kw;

#pragma unroll
            for (int ks = 0; ks < 8; ks++) {
                uint32_t a[4][4];
#pragma unroll
                for (int mt = 0; mt < 4; mt++) {
                    const float* p = Ap + ks * 576 + mt * 16;
                    a[mt][0] = __float_as_uint(p[0]);
                    a[mt][1] = __float_as_uint(p[8]);
                    a[mt][2] = __float_as_uint(p[288]);
                    a[mt][3] = __float_as_uint(p[296]);
                }
                if (ks < 2) {
#pragma unroll
                    for (int nt = 0; nt < 8; nt++) {
                        uint2 bb = *(const uint2*)&Bp[(ks * 8 + nt) * 64 + lane * 2];
#pragma unroll
                        for (int mt = 0; mt < 4; mt++)
                            mma_tf32(acc[mt][nt], a[mt], bb.x, bb.y);
                    }
                } else {
                    int j2 = ((ks - 2) >> 1) * 2;          // 0, 2, 4
                    int fb = 16 + (ks - 2) * 4;
#pragma unroll
                    for (int q = 0; q < 4; q++) {
                        int nt = (q < 2) ? q : (2 + j2 + (q - 2));
                        uint2 bb = *(const uint2*)&Bp[(fb + q) * 64 + lane * 2];
#pragma unroll
                        for (int mt = 0; mt < 4; mt++)
                            mma_tf32(acc[mt][nt], a[mt], bb.x, bb.y);
                    }
                }
            }
            __syncthreads();            // all warps done with slice s (slot reuse)
            if (s + 2 < 125) {
                for (int i = tid; i < 640; i += 128)
                    cp16(bs_u + (uint32_t)((s & 1) * 10240 + i * 16),
                         bf + (s + 2) * 2560 + i * 4);
            }
            asm volatile("cp.async.commit_group;" ::: "memory");  // uniform group count
        }
    }

    // Epilogue: acc holds out[ow][oc'] for this row; invert the oc permutation.
    int base = myod * OS2 + myoh * 52;
#pragma unroll
    for (int mt = 0; mt < 4; mt++) {
        int ow = mt * 16 + (lane >> 2);
#pragma unroll
        for (int nt = 0; nt < 8; nt++) {
            int ocp = nt * 8 + (lane & 3) * 2;
            int oc0 = ocp < 16 ? ocp : 16 + 3 * ((ocp - 16) & 15) + ((ocp - 16) >> 4);
            int op1 = ocp + 1;
            int oc1 = op1 < 16 ? op1 : 16 + 3 * ((op1 - 16) & 15) + ((op1 - 16) >> 4);
            if (ow < 52) {
                out[oc0 * OS3 + base + ow] = acc[mt][nt][0];
                out[oc1 * OS3 + base + ow] = acc[mt][nt][1];
            }
            if (ow + 8 < 52) {
                out[oc0 * OS3 + base + ow + 8] = acc[mt][nt][2];
                out[oc1 * OS3 + base + ow + 8] = acc[mt][nt][3];
            }
        }
    }
}

// ---------------------------------------------------------------------------
extern "C" void kernel_launch(void* const* d_in, const int* in_sizes, int n_in,
                              void* d_out, int out_size) {
    const float* x      = (const float*)d_in[0];   // (1, 64, 56, 56, 56)
    const float* weight = (const float*)d_in[1];   // (5, 1024)
    const float* w_sc0  = (const float*)d_in[2];   // (16, 16)
    const float* w_sc1  = (const float*)d_in[3];   // (16, 16)
    float* out = (float*)d_out;                    // (1, 64, 52, 52, 52)

    cudaFuncSetAttribute(conv_kernel, cudaFuncAttributeMaxDynamicSharedMemorySize, 94208);
    build_kernel<<<125, 256>>>(weight, w_sc0, w_sc1);
    cvt_x_kernel<<<2744, 1024>>>(x);
    conv_kernel<<<676, 128, 94208>>>(out);
}